// round 6
// baseline (speedup 1.0000x reference)
#include <cuda_runtime.h>
#include <cuda_bf16.h>
#include <cstdint>
#include <math.h>

// ---------------------------------------------------------------------------
// Problem constants
// ---------------------------------------------------------------------------
#define BATCH    4
#define SEQ      2048
#define DMODEL   1024
#define NHEADS   16
#define HDIM     64
#define NEG_INF_F (-1e30f)

#define MROWS   (BATCH * SEQ)       // 8192
#define NQKV    (3 * DMODEL)        // 3072

// ---------------------------------------------------------------------------
// Device scratch (bf16 hi/lo splits everywhere)
// ---------------------------------------------------------------------------
__device__ __nv_bfloat16 g_xhi[(size_t)MROWS * DMODEL];
__device__ __nv_bfloat16 g_xlo[(size_t)MROWS * DMODEL];
__device__ __nv_bfloat16 g_ahi[(size_t)MROWS * DMODEL];
__device__ __nv_bfloat16 g_alo[(size_t)MROWS * DMODEL];
// weights, split + transposed to [N][K]
__device__ __nv_bfloat16 g_wqh[(size_t)NQKV * DMODEL];
__device__ __nv_bfloat16 g_wql[(size_t)NQKV * DMODEL];
__device__ __nv_bfloat16 g_woh[(size_t)DMODEL * DMODEL];
__device__ __nv_bfloat16 g_wol[(size_t)DMODEL * DMODEL];
// attention operands: Q (pre-scaled 1/8), K in [bh][s][d]; V transposed [bh][d][s]
__device__ __nv_bfloat16 g_qhi[(size_t)BATCH * NHEADS * SEQ * HDIM];
__device__ __nv_bfloat16 g_qlo[(size_t)BATCH * NHEADS * SEQ * HDIM];
__device__ __nv_bfloat16 g_khi[(size_t)BATCH * NHEADS * SEQ * HDIM];
__device__ __nv_bfloat16 g_klo[(size_t)BATCH * NHEADS * SEQ * HDIM];
__device__ __nv_bfloat16 g_vhi[(size_t)BATCH * NHEADS * HDIM * SEQ];
__device__ __nv_bfloat16 g_vlo[(size_t)BATCH * NHEADS * HDIM * SEQ];

// ---------------------------------------------------------------------------
// Portable PTX helpers (mma.sync / ldmatrix / cp.async — plain compute_103 OK)
// ---------------------------------------------------------------------------
__device__ __forceinline__ uint32_t smem_u32(const void* p) {
    uint32_t a;
    asm("{ .reg .u64 t; cvta.to.shared.u64 t, %1; cvt.u32.u64 %0, t; }"
        : "=r"(a) : "l"(p));
    return a;
}

__device__ __forceinline__ void ldm_x4(uint32_t* r, uint32_t addr) {
    asm volatile("ldmatrix.sync.aligned.m8n8.x4.shared.b16 {%0,%1,%2,%3}, [%4];"
                 : "=r"(r[0]), "=r"(r[1]), "=r"(r[2]), "=r"(r[3]) : "r"(addr));
}

__device__ __forceinline__ void mma16816(float* d, const uint32_t* a, const uint32_t* b) {
    asm volatile(
        "mma.sync.aligned.m16n8k16.row.col.f32.bf16.bf16.f32 "
        "{%0,%1,%2,%3}, {%4,%5,%6,%7}, {%8,%9}, {%0,%1,%2,%3};"
        : "+f"(d[0]), "+f"(d[1]), "+f"(d[2]), "+f"(d[3])
        : "r"(a[0]), "r"(a[1]), "r"(a[2]), "r"(a[3]), "r"(b[0]), "r"(b[1]));
}

__device__ __forceinline__ void cp_async16(uint32_t saddr, const void* gptr) {
    asm volatile("cp.async.cg.shared.global [%0], [%1], 16;"
                 :: "r"(saddr), "l"(gptr));
}
__device__ __forceinline__ void cp_commit() {
    asm volatile("cp.async.commit_group;");
}
template<int N> __device__ __forceinline__ void cp_wait() {
    asm volatile("cp.async.wait_group %0;" :: "n"(N));
}

__device__ __forceinline__ uint32_t cvt_bf16x2(float hi_val, float lo_val) {
    uint32_t r;
    asm("cvt.rn.bf16x2.f32 %0, %1, %2;" : "=r"(r) : "f"(hi_val), "f"(lo_val));
    return r;
}
__device__ __forceinline__ float bf16x2_lo(uint32_t v) {
    __nv_bfloat162 t = *(__nv_bfloat162*)&v; return __bfloat162float(t.x);
}
__device__ __forceinline__ float bf16x2_hi(uint32_t v) {
    __nv_bfloat162 t = *(__nv_bfloat162*)&v; return __bfloat162float(t.y);
}

// ---------------------------------------------------------------------------
// Conversion: x fp32 -> (hi, lo) bf16 split
// ---------------------------------------------------------------------------
__global__ __launch_bounds__(256) void convert_split_kernel(
    const float* __restrict__ src, int n4)
{
    int i = blockIdx.x * 256 + threadIdx.x;
    if (i >= n4) return;
    float4 v = ((const float4*)src)[i];
    __nv_bfloat16 h0 = __float2bfloat16_rn(v.x);
    __nv_bfloat16 h1 = __float2bfloat16_rn(v.y);
    __nv_bfloat16 h2 = __float2bfloat16_rn(v.z);
    __nv_bfloat16 h3 = __float2bfloat16_rn(v.w);
    __nv_bfloat162 ph0; ph0.x = h0; ph0.y = h1;
    __nv_bfloat162 ph1; ph1.x = h2; ph1.y = h3;
    __nv_bfloat162 pl0;
    pl0.x = __float2bfloat16_rn(v.x - __bfloat162float(h0));
    pl0.y = __float2bfloat16_rn(v.y - __bfloat162float(h1));
    __nv_bfloat162 pl1;
    pl1.x = __float2bfloat16_rn(v.z - __bfloat162float(h2));
    pl1.y = __float2bfloat16_rn(v.w - __bfloat162float(h3));
    ((__nv_bfloat162*)g_xhi)[2 * i]     = ph0;
    ((__nv_bfloat162*)g_xhi)[2 * i + 1] = ph1;
    ((__nv_bfloat162*)g_xlo)[2 * i]     = pl0;
    ((__nv_bfloat162*)g_xlo)[2 * i + 1] = pl1;
}

// W [K x N] fp32 -> transposed [N x K] bf16 hi/lo
__global__ __launch_bounds__(256) void transpose_split_kernel(
    const float* __restrict__ src, int sel, int N)
{
    __shared__ float tile[32][33];
    const int K = DMODEL;
    __nv_bfloat16* hi = (sel == 0) ? g_wqh : g_woh;
    __nv_bfloat16* lo = (sel == 0) ? g_wql : g_wol;

    int tx = threadIdx.x;
    int ty = threadIdx.y;
    int n0 = blockIdx.x * 32;
    int k0 = blockIdx.y * 32;

#pragma unroll
    for (int i = 0; i < 4; i++)
        tile[ty + 8 * i][tx] = src[(size_t)(k0 + ty + 8 * i) * N + n0 + tx];
    __syncthreads();
#pragma unroll
    for (int i = 0; i < 4; i++) {
        float v = tile[tx][ty + 8 * i];
        __nv_bfloat16 h = __float2bfloat16_rn(v);
        size_t o = (size_t)(n0 + ty + 8 * i) * K + k0 + tx;
        hi[o] = h;
        lo[o] = __float2bfloat16_rn(v - __bfloat162float(h));
    }
}

// ---------------------------------------------------------------------------
// cp.async double-buffered mma.sync GEMM.
// CTA 128x128, 8 warps 2x4, warp 64x32.  K-chunk 32, 2 stages.
// Stage = 4 tiles (Ah/Al/Bh/Bl) of 128 rows x 32 bf16, 80B padded rows.
// MODE 0: epilogue -> q/k hi/lo [bh][s][d], v hi/lo transposed [bh][d][s].
// MODE 1: plain fp32 store into Cout.
// ---------------------------------------------------------------------------
#define GROWB        80                  // 64B data + 16B pad
#define GTILE_BYTES  (128 * GROWB)       // 10240
#define STAGE_BYTES  (4 * GTILE_BYTES)   // 40960
#define OFF_AL       GTILE_BYTES
#define OFF_BH       (2 * GTILE_BYTES)
#define OFF_BL       (3 * GTILE_BYTES)
#define GEMM_SMEM_BYTES (2 * STAGE_BYTES) // 81920

template<int MODE>
__global__ __launch_bounds__(256) void mma_gemm_kernel(float* __restrict__ Cout)
{
    extern __shared__ char smem[];
    const uint32_t sbase = smem_u32(smem);

    const int tid  = threadIdx.x;
    const int wid  = tid >> 5;
    const int lane = tid & 31;
    const int wm   = wid >> 2;
    const int wn   = wid & 3;
    const int m0   = blockIdx.y * 128;
    const int n0   = blockIdx.x * 128;

    const __nv_bfloat16* Ahi = (MODE == 0) ? g_xhi : g_ahi;
    const __nv_bfloat16* Alo = (MODE == 0) ? g_xlo : g_alo;
    const __nv_bfloat16* Bhi = (MODE == 0) ? g_wqh : g_woh;
    const __nv_bfloat16* Blo = (MODE == 0) ? g_wql : g_wol;

    const uint4* A4h = (const uint4*)Ahi;   // row stride 128 uint4
    const uint4* A4l = (const uint4*)Alo;
    const uint4* B4h = (const uint4*)Bhi;
    const uint4* B4l = (const uint4*)Blo;

    float acc[4][4][4];
#pragma unroll
    for (int i = 0; i < 4; i++)
#pragma unroll
        for (int j = 0; j < 4; j++)
#pragma unroll
            for (int c = 0; c < 4; c++) acc[i][j][c] = 0.f;

    const int a_row = wm * 64 + (lane & 15);
    const int a_col = (lane >> 4) * 8;
    const int b_row = wn * 32 + (lane & 7) + (lane >> 4) * 8;
    const int b_col = ((lane >> 3) & 1) * 8;

    // per-thread staging slots: e = tid + i*256, i in {0,1}
    const int e0_row = tid >> 2;
    const int e0_seg = tid & 3;

    // ---- prefetch helper (macro-ish lambda) ----
    auto prefetch = [&](int kc, int stage) {
        uint32_t sb = sbase + stage * STAGE_BYTES;
#pragma unroll
        for (int i = 0; i < 2; i++) {
            int row = e0_row + i * 64;
            int seg = e0_seg;
            uint32_t soff = sb + (uint32_t)(row * GROWB + seg * 16);
            size_t aidx = (size_t)(m0 + row) * 128 + kc * 4 + seg;
            size_t bidx = (size_t)(n0 + row) * 128 + kc * 4 + seg;
            cp_async16(soff,          A4h + aidx);
            cp_async16(soff + OFF_AL, A4l + aidx);
            cp_async16(soff + OFF_BH, B4h + bidx);
            cp_async16(soff + OFF_BL, B4l + bidx);
        }
        cp_commit();
    };

    prefetch(0, 0);

    for (int kc = 0; kc < 32; kc++) {
        const int cur = kc & 1;
        if (kc + 1 < 32) prefetch(kc + 1, cur ^ 1);
        else             cp_commit();          // empty group keeps the count uniform
        cp_wait<1>();
        __syncthreads();

        const uint32_t stg = sbase + cur * STAGE_BYTES;
#pragma unroll
        for (int ks = 0; ks < 2; ks++) {
            uint32_t a_addr = stg + (uint32_t)(a_row * GROWB + (ks * 16 + a_col) * 2);
            uint32_t b_addr = stg + OFF_BH +
                              (uint32_t)(b_row * GROWB + (ks * 16 + b_col) * 2);

            uint32_t af[4][4];
            uint32_t bh[4][2], bl[4][2];

#pragma unroll
            for (int mi = 0; mi < 4; mi++)
                ldm_x4(af[mi], a_addr + mi * 16 * GROWB);
#pragma unroll
            for (int np = 0; np < 2; np++) {
                uint32_t r[4];
                ldm_x4(r, b_addr + np * 16 * GROWB);
                bh[np * 2][0] = r[0]; bh[np * 2][1] = r[1];
                bh[np * 2 + 1][0] = r[2]; bh[np * 2 + 1][1] = r[3];
                ldm_x4(r, b_addr + (OFF_BL - OFF_BH) + np * 16 * GROWB);
                bl[np * 2][0] = r[0]; bl[np * 2][1] = r[1];
                bl[np * 2 + 1][0] = r[2]; bl[np * 2 + 1][1] = r[3];
            }

#pragma unroll
            for (int mi = 0; mi < 4; mi++)
#pragma unroll
                for (int ni = 0; ni < 4; ni++)
                    mma16816(acc[mi][ni], af[mi], bh[ni]);
#pragma unroll
            for (int mi = 0; mi < 4; mi++)
#pragma unroll
                for (int ni = 0; ni < 4; ni++)
                    mma16816(acc[mi][ni], af[mi], bl[ni]);
#pragma unroll
            for (int mi = 0; mi < 4; mi++)
                ldm_x4(af[mi], a_addr + OFF_AL + mi * 16 * GROWB);
#pragma unroll
            for (int mi = 0; mi < 4; mi++)
#pragma unroll
                for (int ni = 0; ni < 4; ni++)
                    mma16816(acc[mi][ni], af[mi], bh[ni]);
        }
        __syncthreads();
    }

    const int er = lane >> 2;
    const int ec = (lane & 3) * 2;
#pragma unroll
    for (int mi = 0; mi < 4; mi++) {
#pragma unroll
        for (int rr = 0; rr < 2; rr++) {
            int m = m0 + wm * 64 + mi * 16 + er + rr * 8;
            int b = m >> 11;
            int s = m & 2047;
#pragma unroll
            for (int ni = 0; ni < 4; ni++) {
#pragma unroll
                for (int cc = 0; cc < 2; cc++) {
                    int n = n0 + wn * 32 + ni * 8 + ec + cc;
                    float v = acc[mi][ni][rr * 2 + cc];
                    if (MODE == 0) {
                        int t = n >> 10;
                        int h = (n >> 6) & 15;
                        int d = n & 63;
                        if (t == 0) v *= 0.125f;   // fold 1/sqrt(hd) into Q
                        __nv_bfloat16 hv = __float2bfloat16_rn(v);
                        __nv_bfloat16 lv = __float2bfloat16_rn(v - __bfloat162float(hv));
                        int bh_i = b * NHEADS + h;
                        if (t == 2) {
                            size_t o = ((size_t)bh_i * HDIM + d) * SEQ + s;
                            g_vhi[o] = hv; g_vlo[o] = lv;
                        } else {
                            size_t o = ((size_t)bh_i * SEQ + s) * HDIM + d;
                            if (t == 0) { g_qhi[o] = hv; g_qlo[o] = lv; }
                            else        { g_khi[o] = hv; g_klo[o] = lv; }
                        }
                    } else {
                        Cout[(size_t)m * DMODEL + n] = v;
                    }
                }
            }
        }
    }
}

// ---------------------------------------------------------------------------
// Tensorized flash attention (unchanged from passing R4 kernel).
// ---------------------------------------------------------------------------
#define ROWB      144
#define AQH_OFF   0
#define AQL_OFF   18432
#define AKH_OFF   36864
#define AKL_OFF   55296
#define AVH_OFF   73728
#define AVL_OFF   91136
#define ABIAS_OFF 108544
#define ATT_SMEM  109056
#define VROWB     272     // 128 keys * 2B + 16B pad

__global__ __launch_bounds__(256) void flash_attn_mma_kernel(const int* __restrict__ mask)
{
    extern __shared__ char smem[];
    const uint32_t sbase = smem_u32(smem);
    const int tid  = threadIdx.x;
    const int wid  = tid >> 5;
    const int lane = tid & 31;
    const int qb   = blockIdx.x;
    const int bh   = blockIdx.y;
    const int b    = bh >> 4;
    const int h    = bh & 15;
    const int q0   = qb * 128;
    const int r0   = wid * 16;
    const int er   = lane >> 2;
    const int ec   = (lane & 3) * 2;

    // load Q hi/lo tile (128 x 64)
    {
        const uint4* Qh4 = (const uint4*)(g_qhi + ((size_t)bh * SEQ + q0) * HDIM);
        const uint4* Ql4 = (const uint4*)(g_qlo + ((size_t)bh * SEQ + q0) * HDIM);
#pragma unroll
        for (int it = 0; it < 4; it++) {
            int e = tid + it * 256;
            int row = e >> 3, seg = e & 7;
            uint32_t soff = (uint32_t)(row * ROWB + seg * 16);
            *(uint4*)(smem + AQH_OFF + soff) = Qh4[row * 8 + seg];
            *(uint4*)(smem + AQL_OFF + soff) = Ql4[row * 8 + seg];
        }
    }

    float m_s[2] = {-1e30f, -1e30f};
    float l_s[2] = {0.f, 0.f};
    float o[8][4];
#pragma unroll
    for (int i = 0; i < 8; i++)
#pragma unroll
        for (int c = 0; c < 4; c++) o[i][c] = 0.f;

    const uint32_t a_base = sbase + (uint32_t)((r0 + (lane & 15)) * ROWB + ((lane >> 4) * 8) * 2);
    const uint32_t b_base = sbase + AKH_OFF +
        (uint32_t)(((lane & 7) + (lane >> 4) * 8) * ROWB + (((lane >> 3) & 1) * 8) * 2);
    const uint32_t v_base = sbase + AVH_OFF +
        (uint32_t)(((lane & 7) + (lane >> 4) * 8) * VROWB + (((lane >> 3) & 1) * 8) * 2);

    for (int kb = 0; kb <= qb; kb++) {
        const int j0 = kb * 128;
        {
            const uint4* Kh4 = (const uint4*)(g_khi + ((size_t)bh * SEQ + j0) * HDIM);
            const uint4* Kl4 = (const uint4*)(g_klo + ((size_t)bh * SEQ + j0) * HDIM);
#pragma unroll
            for (int it = 0; it < 4; it++) {
                int e = tid + it * 256;
                int row = e >> 3, seg = e & 7;
                uint32_t soff = (uint32_t)(row * ROWB + seg * 16);
                *(uint4*)(smem + AKH_OFF + soff) = Kh4[row * 8 + seg];
                *(uint4*)(smem + AKL_OFF + soff) = Kl4[row * 8 + seg];
            }
#pragma unroll
            for (int it = 0; it < 4; it++) {
                int e = tid + it * 256;
                int d = e >> 4, seg = e & 15;
                uint32_t soff = (uint32_t)(d * VROWB + seg * 16);
                size_t gi = (((size_t)(bh * HDIM + d) * SEQ + j0) >> 3) + seg;
                *(uint4*)(smem + AVH_OFF + soff) = ((const uint4*)g_vhi)[gi];
                *(uint4*)(smem + AVL_OFF + soff) = ((const uint4*)g_vlo)[gi];
            }
            if (tid < 128)
                *(float*)(smem + ABIAS_OFF + tid * 4) =
                    (mask[b * SEQ + j0 + tid] == 0) ? NEG_INF_F : 0.f;
        }
        __syncthreads();

        float sc[16][4];
#pragma unroll
        for (int i = 0; i < 16; i++)
#pragma unroll
            for (int c = 0; c < 4; c++) sc[i][c] = 0.f;

#pragma unroll
        for (int ks = 0; ks < 4; ks++) {
            uint32_t qh[4], ql[4];
            ldm_x4(qh, a_base + AQH_OFF + ks * 32);
            ldm_x4(ql, a_base + AQL_OFF + ks * 32);
#pragma unroll
            for (int np = 0; np < 8; np++) {
                uint32_t kh[4], kl[4];
                ldm_x4(kh, b_base + ks * 32 + np * 16 * ROWB);
                ldm_x4(kl, b_base + (AKL_OFF - AKH_OFF) + ks * 32 + np * 16 * ROWB);
                mma16816(sc[2 * np],     qh, kh);
                mma16816(sc[2 * np + 1], qh, kh + 2);
                mma16816(sc[2 * np],     qh, kl);
                mma16816(sc[2 * np + 1], qh, kl + 2);
                mma16816(sc[2 * np],     ql, kh);
                mma16816(sc[2 * np + 1], ql, kh + 2);
            }
        }

#pragma unroll
        for (int nf = 0; nf < 16; nf++) {
            float2 bv = *(const float2*)(smem + ABIAS_OFF + (nf * 8 + ec) * 4);
            sc[nf][0] += bv.x; sc[nf][1] += bv.y;
            sc[nf][2] += bv.x; sc[nf][3] += bv.y;
        }
        if (kb == qb) {
            int rl0 = r0 + er, rl1 = r0 + er + 8;
#pragma unroll
            for (int nf = 0; nf < 16; nf++) {
                int c0 = nf * 8 + ec, c1 = c0 + 1;
                if (c0 > rl0) sc[nf][0] = NEG_INF_F;
                if (c1 > rl0) sc[nf][1] = NEG_INF_F;
                if (c0 > rl1) sc[nf][2] = NEG_INF_F;
                if (c1 > rl1) sc[nf][3] = NEG_INF_F;
            }
        }

#pragma unroll
        for (int rr = 0; rr < 2; rr++) {
            float bm = -1e30f;
#pragma unroll
            for (int nf = 0; nf < 16; nf++)
                bm = fmaxf(bm, fmaxf(sc[nf][rr * 2], sc[nf][rr * 2 + 1]));
            bm = fmaxf(bm, __shfl_xor_sync(0xffffffffu, bm, 1));
            bm = fmaxf(bm, __shfl_xor_sync(0xffffffffu, bm, 2));
            float m_new = fmaxf(fmaxf(m_s[rr], bm), -1e29f);
            float alpha = __expf(m_s[rr] - m_new);
            float ls = 0.f;
#pragma unroll
            for (int nf = 0; nf < 16; nf++) {
                float p0 = __expf(sc[nf][rr * 2]     - m_new);
                float p1 = __expf(sc[nf][rr * 2 + 1] - m_new);
                sc[nf][rr * 2] = p0; sc[nf][rr * 2 + 1] = p1;
                ls += p0 + p1;
            }
            ls += __shfl_xor_sync(0xffffffffu, ls, 1);
            ls += __shfl_xor_sync(0xffffffffu, ls, 2);
            l_s[rr] = l_s[rr] * alpha + ls;
            m_s[rr] = m_new;
#pragma unroll
            for (int nf = 0; nf < 8; nf++) {
                o[nf][rr * 2] *= alpha; o[nf][rr * 2 + 1] *= alpha;
            }
        }

#pragma unroll
        for (int ks = 0; ks < 8; ks++) {
            uint32_t ah[4], al[4];
            ah[0] = cvt_bf16x2(sc[2 * ks][1], sc[2 * ks][0]);
            ah[1] = cvt_bf16x2(sc[2 * ks][3], sc[2 * ks][2]);
            ah[2] = cvt_bf16x2(sc[2 * ks + 1][1], sc[2 * ks + 1][0]);
            ah[3] = cvt_bf16x2(sc[2 * ks + 1][3], sc[2 * ks + 1][2]);
            al[0] = cvt_bf16x2(sc[2 * ks][1] - bf16x2_hi(ah[0]),
                               sc[2 * ks][0] - bf16x2_lo(ah[0]));
            al[1] = cvt_bf16x2(sc[2 * ks][3] - bf16x2_hi(ah[1]),
                               sc[2 * ks][2] - bf16x2_lo(ah[1]));
            al[2] = cvt_bf16x2(sc[2 * ks + 1][1] - bf16x2_hi(ah[2]),
                               sc[2 * ks + 1][0] - bf16x2_lo(ah[2]));
            al[3] = cvt_bf16x2(sc[2 * ks + 1][3] - bf16x2_hi(ah[3]),
                               sc[2 * ks + 1][2] - bf16x2_lo(ah[3]));
#pragma unroll
            for (int np = 0; np < 4; np++) {
                uint32_t vh[4], vl[4];
                ldm_x4(vh, v_base + ks * 32 + np * 16 * VROWB);
                ldm_x4(vl, v_base + (AVL_OFF - AVH_OFF) + ks * 32 + np * 16 * VROWB);
                mma16816(o[2 * np],     ah, vh);
                mma16816(o[2 * np + 1], ah, vh + 2);
                mma16816(o[2 * np],     al, vh);
                mma16816(o[2 * np + 1], al, vh + 2);
                mma16816(o[2 * np],     ah, vl);
                mma16816(o[2 * np + 1], ah, vl + 2);
            }
        }
        __syncthreads();
    }

#pragma unroll
    for (int rr = 0; rr < 2; rr++) {
        float inv = 1.f / l_s[rr];
        int row = q0 + r0 + er + rr * 8;
        size_t base = ((size_t)b * SEQ + row) * DMODEL + h * HDIM;
#pragma unroll
        for (int nf = 0; nf < 8; nf++) {
            int d = nf * 8 + ec;
            float v0 = o[nf][rr * 2] * inv;
            float v1 = o[nf][rr * 2 + 1] * inv;
            __nv_bfloat162 hh;
            hh.x = __float2bfloat16_rn(v0);
            hh.y = __float2bfloat16_rn(v1);
            __nv_bfloat162 ll;
            ll.x = __float2bfloat16_rn(v0 - __bfloat162float(hh.x));
            ll.y = __float2bfloat16_rn(v1 - __bfloat162float(hh.y));
            *(__nv_bfloat162*)(g_ahi + base + d) = hh;
            *(__nv_bfloat162*)(g_alo + base + d) = ll;
        }
    }
}

// ---------------------------------------------------------------------------
// Entry point
// ---------------------------------------------------------------------------
extern "C" void kernel_launch(void* const* d_in, const int* in_sizes, int n_in,
                              void* d_out, int out_size)
{
    const float* x      = (const float*)d_in[0];   // (4, 2048, 1024) fp32
    const int*   mask   = (const int*)d_in[1];     // (4, 2048) int32
    const float* w_qkv  = (const float*)d_in[2];   // (1024, 3072) fp32
    const float* w_out  = (const float*)d_in[3];   // (1024, 1024) fp32
    float*       out    = (float*)d_out;           // (4, 2048, 1024) fp32

    (void)in_sizes; (void)n_in; (void)out_size;

    cudaFuncSetAttribute(mma_gemm_kernel<0>,
                         cudaFuncAttributeMaxDynamicSharedMemorySize, GEMM_SMEM_BYTES);
    cudaFuncSetAttribute(mma_gemm_kernel<1>,
                         cudaFuncAttributeMaxDynamicSharedMemorySize, GEMM_SMEM_BYTES);
    cudaFuncSetAttribute(flash_attn_mma_kernel,
                         cudaFuncAttributeMaxDynamicSharedMemorySize, ATT_SMEM);

    // prep: bf16 splits
    convert_split_kernel<<<(MROWS * DMODEL / 4 + 255) / 256, 256>>>(x, MROWS * DMODEL / 4);
    transpose_split_kernel<<<dim3(NQKV / 32, DMODEL / 32), dim3(32, 8)>>>(w_qkv, 0, NQKV);
    transpose_split_kernel<<<dim3(DMODEL / 32, DMODEL / 32), dim3(32, 8)>>>(w_out, 1, DMODEL);

    // 1) QKV projection -> q/k hi/lo [bh][s][d], v hi/lo transposed [bh][d][s]
    mma_gemm_kernel<0><<<dim3(NQKV / 128, MROWS / 128), 256, GEMM_SMEM_BYTES>>>(nullptr);

    // 2) Tensorized causal flash attention -> g_ahi/g_alo (B,S,D)
    flash_attn_mma_kernel<<<dim3(SEQ / 128, BATCH * NHEADS), 256, ATT_SMEM>>>(mask);

    // 3) Output projection -> d_out
    mma_gemm_kernel<1><<<dim3(DMODEL / 128, MROWS / 128), 256, GEMM_SMEM_BYTES>>>(out);
}

// round 7
// speedup vs baseline: 1.2861x; 1.2861x over previous
#include <cuda_runtime.h>
#include <cuda_fp16.h>
#include <cstdint>
#include <math.h>

// ---------------------------------------------------------------------------
// Problem constants
// ---------------------------------------------------------------------------
#define BATCH    4
#define SEQ      2048
#define DMODEL   1024
#define NHEADS   16
#define HDIM     64
#define NEG_INF_F (-1e30f)

#define MROWS   (BATCH * SEQ)       // 8192
#define NQKV    (3 * DMODEL)        // 3072

// ---------------------------------------------------------------------------
// Device scratch (fp16 hi/lo splits)
// ---------------------------------------------------------------------------
__device__ __half g_xhi[(size_t)MROWS * DMODEL];
__device__ __half g_xlo[(size_t)MROWS * DMODEL];
__device__ __half g_ahi[(size_t)MROWS * DMODEL];
__device__ __half g_alo[(size_t)MROWS * DMODEL];
// weights, hi only (2-term scheme needs full A split, B hi), transposed [N][K]
__device__ __half g_wqh[(size_t)NQKV * DMODEL];
__device__ __half g_woh[(size_t)DMODEL * DMODEL];
// attention operands: Q (pre-scaled 1/8) hi/lo, K hi/lo in [bh][s][d];
// V hi only, transposed [bh][d][s]
__device__ __half g_qhi[(size_t)BATCH * NHEADS * SEQ * HDIM];
__device__ __half g_qlo[(size_t)BATCH * NHEADS * SEQ * HDIM];
__device__ __half g_khi[(size_t)BATCH * NHEADS * SEQ * HDIM];
__device__ __half g_klo[(size_t)BATCH * NHEADS * SEQ * HDIM];
__device__ __half g_vhi[(size_t)BATCH * NHEADS * HDIM * SEQ];

// ---------------------------------------------------------------------------
// Portable PTX helpers (mma.sync / ldmatrix — plain compute_103 OK)
// ---------------------------------------------------------------------------
__device__ __forceinline__ uint32_t smem_u32(const void* p) {
    uint32_t a;
    asm("{ .reg .u64 t; cvta.to.shared.u64 t, %1; cvt.u32.u64 %0, t; }"
        : "=r"(a) : "l"(p));
    return a;
}

__device__ __forceinline__ void ldm_x4(uint32_t* r, uint32_t addr) {
    asm volatile("ldmatrix.sync.aligned.m8n8.x4.shared.b16 {%0,%1,%2,%3}, [%4];"
                 : "=r"(r[0]), "=r"(r[1]), "=r"(r[2]), "=r"(r[3]) : "r"(addr));
}

__device__ __forceinline__ void mma16816(float* d, const uint32_t* a, const uint32_t* b) {
    asm volatile(
        "mma.sync.aligned.m16n8k16.row.col.f32.f16.f16.f32 "
        "{%0,%1,%2,%3}, {%4,%5,%6,%7}, {%8,%9}, {%0,%1,%2,%3};"
        : "+f"(d[0]), "+f"(d[1]), "+f"(d[2]), "+f"(d[3])
        : "r"(a[0]), "r"(a[1]), "r"(a[2]), "r"(a[3]), "r"(b[0]), "r"(b[1]));
}

// pack two fp32 into f16x2: high half = hi_val, low half = lo_val
__device__ __forceinline__ uint32_t cvt_f16x2(float hi_val, float lo_val) {
    uint32_t r;
    asm("cvt.rn.f16x2.f32 %0, %1, %2;" : "=r"(r) : "f"(hi_val), "f"(lo_val));
    return r;
}
__device__ __forceinline__ float f16x2_lo(uint32_t v) {
    __half2 t = *(__half2*)&v; return __half2float(t.x);
}
__device__ __forceinline__ float f16x2_hi(uint32_t v) {
    __half2 t = *(__half2*)&v; return __half2float(t.y);
}

// ---------------------------------------------------------------------------
// Conversion: x fp32 -> (hi, lo) fp16 split
// ---------------------------------------------------------------------------
__global__ __launch_bounds__(256) void convert_split_kernel(
    const float* __restrict__ src, int n4)
{
    int i = blockIdx.x * 256 + threadIdx.x;
    if (i >= n4) return;
    float4 v = ((const float4*)src)[i];
    __half h0 = __float2half_rn(v.x);
    __half h1 = __float2half_rn(v.y);
    __half h2 = __float2half_rn(v.z);
    __half h3 = __float2half_rn(v.w);
    __half2 ph0; ph0.x = h0; ph0.y = h1;
    __half2 ph1; ph1.x = h2; ph1.y = h3;
    __half2 pl0;
    pl0.x = __float2half_rn(v.x - __half2float(h0));
    pl0.y = __float2half_rn(v.y - __half2float(h1));
    __half2 pl1;
    pl1.x = __float2half_rn(v.z - __half2float(h2));
    pl1.y = __float2half_rn(v.w - __half2float(h3));
    ((__half2*)g_xhi)[2 * i]     = ph0;
    ((__half2*)g_xhi)[2 * i + 1] = ph1;
    ((__half2*)g_xlo)[2 * i]     = pl0;
    ((__half2*)g_xlo)[2 * i + 1] = pl1;
}

// W [K x N] fp32 -> transposed [N x K] fp16 hi only
__global__ __launch_bounds__(256) void transpose_split_kernel(
    const float* __restrict__ src, int sel, int N)
{
    __shared__ float tile[32][33];
    const int K = DMODEL;
    __half* hi = (sel == 0) ? g_wqh : g_woh;

    int tx = threadIdx.x;
    int ty = threadIdx.y;
    int n0 = blockIdx.x * 32;
    int k0 = blockIdx.y * 32;

#pragma unroll
    for (int i = 0; i < 4; i++)
        tile[ty + 8 * i][tx] = src[(size_t)(k0 + ty + 8 * i) * N + n0 + tx];
    __syncthreads();
#pragma unroll
    for (int i = 0; i < 4; i++) {
        float v = tile[tx][ty + 8 * i];
        hi[(size_t)(n0 + ty + 8 * i) * K + k0 + tx] = __float2half_rn(v);
    }
}

// ---------------------------------------------------------------------------
// mma.sync GEMM, 2-term fp16: D = (Ah + Al) * Bh  (= A * Bh exactly).
// CTA 128x128, 8 warps 2x4, warp 64x32, K-chunk 64, single-buffered.
// Tiles: Ah, Al, Bh (128 x 64 fp16, 144B padded rows).
// MODE 0: epilogue -> q/k hi/lo [bh][s][d], v hi transposed [bh][d][s].
// MODE 1: plain fp32 store into Cout.
// ---------------------------------------------------------------------------
#define ROWB 144
#define TILE_BYTES (128 * ROWB)           // 18432
#define OFF_AL TILE_BYTES
#define OFF_BH (2 * TILE_BYTES)
#define GEMM_SMEM_BYTES (3 * TILE_BYTES)  // 55296

template<int MODE>
__global__ __launch_bounds__(256) void mma_gemm_kernel(float* __restrict__ Cout)
{
    extern __shared__ char smem[];
    const uint32_t sbase = smem_u32(smem);

    const int tid  = threadIdx.x;
    const int wid  = tid >> 5;
    const int lane = tid & 31;
    const int wm   = wid >> 2;
    const int wn   = wid & 3;
    const int m0   = blockIdx.y * 128;
    const int n0   = blockIdx.x * 128;

    const __half* Ahi = (MODE == 0) ? g_xhi : g_ahi;
    const __half* Alo = (MODE == 0) ? g_xlo : g_alo;
    const __half* Bhi = (MODE == 0) ? g_wqh : g_woh;

    const uint4* A4h = (const uint4*)Ahi;   // row stride = 128 uint4
    const uint4* A4l = (const uint4*)Alo;
    const uint4* B4h = (const uint4*)Bhi;

    float acc[4][4][4];
#pragma unroll
    for (int i = 0; i < 4; i++)
#pragma unroll
        for (int j = 0; j < 4; j++)
#pragma unroll
            for (int c = 0; c < 4; c++) acc[i][j][c] = 0.f;

    const int a_row = wm * 64 + (lane & 15);
    const int a_col = (lane >> 4) * 8;
    const int b_row = wn * 32 + (lane & 7) + (lane >> 4) * 8;
    const int b_col = ((lane >> 3) & 1) * 8;

    for (int kc = 0; kc < 16; kc++) {
        // ---- stage 3 tiles: 128 rows x 64 fp16 each ----
#pragma unroll
        for (int it = 0; it < 4; it++) {
            int e   = tid + it * 256;
            int row = e >> 3;
            int seg = e & 7;
            uint32_t soff = (uint32_t)(row * ROWB + seg * 16);
            size_t aidx = (size_t)(m0 + row) * 128 + kc * 8 + seg;
            size_t bidx = (size_t)(n0 + row) * 128 + kc * 8 + seg;
            uint4 vah = A4h[aidx];
            uint4 val = A4l[aidx];
            uint4 vbh = B4h[bidx];
            *(uint4*)(smem + soff)          = vah;
            *(uint4*)(smem + OFF_AL + soff) = val;
            *(uint4*)(smem + OFF_BH + soff) = vbh;
        }
        __syncthreads();

#pragma unroll
        for (int ks = 0; ks < 4; ks++) {
            uint32_t a_addr = sbase + (uint32_t)(a_row * ROWB + (ks * 16 + a_col) * 2);
            uint32_t b_addr = sbase + OFF_BH +
                              (uint32_t)(b_row * ROWB + (ks * 16 + b_col) * 2);

            uint32_t af[4][4];
            uint32_t bh[4][2];

#pragma unroll
            for (int mi = 0; mi < 4; mi++)
                ldm_x4(af[mi], a_addr + mi * 16 * ROWB);
#pragma unroll
            for (int np = 0; np < 2; np++) {
                uint32_t r[4];
                ldm_x4(r, b_addr + np * 16 * ROWB);
                bh[np * 2][0] = r[0]; bh[np * 2][1] = r[1];
                bh[np * 2 + 1][0] = r[2]; bh[np * 2 + 1][1] = r[3];
            }

            // Ah * Bh
#pragma unroll
            for (int mi = 0; mi < 4; mi++)
#pragma unroll
                for (int ni = 0; ni < 4; ni++)
                    mma16816(acc[mi][ni], af[mi], bh[ni]);
            // Al * Bh (reload A frags as lo)
#pragma unroll
            for (int mi = 0; mi < 4; mi++)
                ldm_x4(af[mi], a_addr + OFF_AL + mi * 16 * ROWB);
#pragma unroll
            for (int mi = 0; mi < 4; mi++)
#pragma unroll
                for (int ni = 0; ni < 4; ni++)
                    mma16816(acc[mi][ni], af[mi], bh[ni]);
        }
        __syncthreads();
    }

    const int er = lane >> 2;
    const int ec = (lane & 3) * 2;
#pragma unroll
    for (int mi = 0; mi < 4; mi++) {
#pragma unroll
        for (int rr = 0; rr < 2; rr++) {
            int m = m0 + wm * 64 + mi * 16 + er + rr * 8;
            int b = m >> 11;
            int s = m & 2047;
#pragma unroll
            for (int ni = 0; ni < 4; ni++) {
#pragma unroll
                for (int cc = 0; cc < 2; cc++) {
                    int n = n0 + wn * 32 + ni * 8 + ec + cc;
                    float v = acc[mi][ni][rr * 2 + cc];
                    if (MODE == 0) {
                        int t = n >> 10;
                        int h = (n >> 6) & 15;
                        int d = n & 63;
                        if (t == 0) v *= 0.125f;   // fold 1/sqrt(hd) into Q
                        __half hv = __float2half_rn(v);
                        int bh_i = b * NHEADS + h;
                        if (t == 2) {
                            g_vhi[((size_t)bh_i * HDIM + d) * SEQ + s] = hv;
                        } else {
                            __half lv = __float2half_rn(v - __half2float(hv));
                            size_t o = ((size_t)bh_i * SEQ + s) * HDIM + d;
                            if (t == 0) { g_qhi[o] = hv; g_qlo[o] = lv; }
                            else        { g_khi[o] = hv; g_klo[o] = lv; }
                        }
                    } else {
                        Cout[(size_t)m * DMODEL + n] = v;
                    }
                }
            }
        }
    }
}

// ---------------------------------------------------------------------------
// Tensorized flash attention (fp16).
// QK = Qh*Kh + Qh*Kl + Ql*Kh (3-term, score precision);
// PV = Ph*Vh + Pl*Vh (= P*Vh exactly; V hi only).
// grid = (S/128, B*H); 256 threads = 8 warps; warp w owns rows w*16..+15.
// Epilogue emits fp16 hi/lo (g_ahi/g_alo) for the output projection.
// ---------------------------------------------------------------------------
#define AQH_OFF   0
#define AQL_OFF   18432
#define AKH_OFF   36864
#define AKL_OFF   55296
#define AVH_OFF   73728
#define ABIAS_OFF 91136     // AVH + 64*272
#define ATT_SMEM  91648
#define VROWB     272       // 128 keys * 2B + 16B pad

__global__ __launch_bounds__(256) void flash_attn_mma_kernel(const int* __restrict__ mask)
{
    extern __shared__ char smem[];
    const uint32_t sbase = smem_u32(smem);
    const int tid  = threadIdx.x;
    const int wid  = tid >> 5;
    const int lane = tid & 31;
    const int qb   = blockIdx.x;
    const int bh   = blockIdx.y;
    const int b    = bh >> 4;
    const int h    = bh & 15;
    const int q0   = qb * 128;
    const int r0   = wid * 16;
    const int er   = lane >> 2;
    const int ec   = (lane & 3) * 2;

    // load Q hi/lo tile (128 x 64)
    {
        const uint4* Qh4 = (const uint4*)(g_qhi + ((size_t)bh * SEQ + q0) * HDIM);
        const uint4* Ql4 = (const uint4*)(g_qlo + ((size_t)bh * SEQ + q0) * HDIM);
#pragma unroll
        for (int it = 0; it < 4; it++) {
            int e = tid + it * 256;
            int row = e >> 3, seg = e & 7;
            uint32_t soff = (uint32_t)(row * ROWB + seg * 16);
            *(uint4*)(smem + AQH_OFF + soff) = Qh4[row * 8 + seg];
            *(uint4*)(smem + AQL_OFF + soff) = Ql4[row * 8 + seg];
        }
    }

    float m_s[2] = {-1e30f, -1e30f};
    float l_s[2] = {0.f, 0.f};
    float o[8][4];
#pragma unroll
    for (int i = 0; i < 8; i++)
#pragma unroll
        for (int c = 0; c < 4; c++) o[i][c] = 0.f;

    const uint32_t a_base = sbase + (uint32_t)((r0 + (lane & 15)) * ROWB + ((lane >> 4) * 8) * 2);
    const uint32_t b_base = sbase + AKH_OFF +
        (uint32_t)(((lane & 7) + (lane >> 4) * 8) * ROWB + (((lane >> 3) & 1) * 8) * 2);
    const uint32_t v_base = sbase + AVH_OFF +
        (uint32_t)(((lane & 7) + (lane >> 4) * 8) * VROWB + (((lane >> 3) & 1) * 8) * 2);

    for (int kb = 0; kb <= qb; kb++) {
        const int j0 = kb * 128;
        // ---- stage K hi/lo (128 x 64), V hi (64 x 128), mask bias ----
        {
            const uint4* Kh4 = (const uint4*)(g_khi + ((size_t)bh * SEQ + j0) * HDIM);
            const uint4* Kl4 = (const uint4*)(g_klo + ((size_t)bh * SEQ + j0) * HDIM);
#pragma unroll
            for (int it = 0; it < 4; it++) {
                int e = tid + it * 256;
                int row = e >> 3, seg = e & 7;
                uint32_t soff = (uint32_t)(row * ROWB + seg * 16);
                *(uint4*)(smem + AKH_OFF + soff) = Kh4[row * 8 + seg];
                *(uint4*)(smem + AKL_OFF + soff) = Kl4[row * 8 + seg];
            }
#pragma unroll
            for (int it = 0; it < 4; it++) {
                int e = tid + it * 256;
                int d = e >> 4, seg = e & 15;
                uint32_t soff = (uint32_t)(d * VROWB + seg * 16);
                size_t gi = (((size_t)(bh * HDIM + d) * SEQ + j0) >> 3) + seg;
                *(uint4*)(smem + AVH_OFF + soff) = ((const uint4*)g_vhi)[gi];
            }
            if (tid < 128)
                *(float*)(smem + ABIAS_OFF + tid * 4) =
                    (mask[b * SEQ + j0 + tid] == 0) ? NEG_INF_F : 0.f;
        }
        __syncthreads();

        // ---- scores: 16 n-frags x 4 k-steps x 3 terms ----
        float sc[16][4];
#pragma unroll
        for (int i = 0; i < 16; i++)
#pragma unroll
            for (int c = 0; c < 4; c++) sc[i][c] = 0.f;

#pragma unroll
        for (int ks = 0; ks < 4; ks++) {
            uint32_t qh[4], ql[4];
            ldm_x4(qh, a_base + AQH_OFF + ks * 32);
            ldm_x4(ql, a_base + AQL_OFF + ks * 32);
#pragma unroll
            for (int np = 0; np < 8; np++) {
                uint32_t kh[4], kl[4];
                ldm_x4(kh, b_base + ks * 32 + np * 16 * ROWB);
                ldm_x4(kl, b_base + (AKL_OFF - AKH_OFF) + ks * 32 + np * 16 * ROWB);
                mma16816(sc[2 * np],     qh, kh);
                mma16816(sc[2 * np + 1], qh, kh + 2);
                mma16816(sc[2 * np],     qh, kl);
                mma16816(sc[2 * np + 1], qh, kl + 2);
                mma16816(sc[2 * np],     ql, kh);
                mma16816(sc[2 * np + 1], ql, kh + 2);
            }
        }

        // ---- pad-mask bias + causal (diagonal block only) ----
#pragma unroll
        for (int nf = 0; nf < 16; nf++) {
            float2 bv = *(const float2*)(smem + ABIAS_OFF + (nf * 8 + ec) * 4);
            sc[nf][0] += bv.x; sc[nf][1] += bv.y;
            sc[nf][2] += bv.x; sc[nf][3] += bv.y;
        }
        if (kb == qb) {
            int rl0 = r0 + er, rl1 = r0 + er + 8;
#pragma unroll
            for (int nf = 0; nf < 16; nf++) {
                int c0 = nf * 8 + ec, c1 = c0 + 1;
                if (c0 > rl0) sc[nf][0] = NEG_INF_F;
                if (c1 > rl0) sc[nf][1] = NEG_INF_F;
                if (c0 > rl1) sc[nf][2] = NEG_INF_F;
                if (c1 > rl1) sc[nf][3] = NEG_INF_F;
            }
        }

        // ---- online softmax (rows er / er+8; reduce over lane quads) ----
#pragma unroll
        for (int rr = 0; rr < 2; rr++) {
            float bm = -1e30f;
#pragma unroll
            for (int nf = 0; nf < 16; nf++)
                bm = fmaxf(bm, fmaxf(sc[nf][rr * 2], sc[nf][rr * 2 + 1]));
            bm = fmaxf(bm, __shfl_xor_sync(0xffffffffu, bm, 1));
            bm = fmaxf(bm, __shfl_xor_sync(0xffffffffu, bm, 2));
            float m_new = fmaxf(fmaxf(m_s[rr], bm), -1e29f);
            float alpha = __expf(m_s[rr] - m_new);
            float ls = 0.f;
#pragma unroll
            for (int nf = 0; nf < 16; nf++) {
                float p0 = __expf(sc[nf][rr * 2]     - m_new);
                float p1 = __expf(sc[nf][rr * 2 + 1] - m_new);
                sc[nf][rr * 2] = p0; sc[nf][rr * 2 + 1] = p1;
                ls += p0 + p1;
            }
            ls += __shfl_xor_sync(0xffffffffu, ls, 1);
            ls += __shfl_xor_sync(0xffffffffu, ls, 2);
            l_s[rr] = l_s[rr] * alpha + ls;
            m_s[rr] = m_new;
#pragma unroll
            for (int nf = 0; nf < 8; nf++) {
                o[nf][rr * 2] *= alpha; o[nf][rr * 2 + 1] *= alpha;
            }
        }

        // ---- PV: P hi/lo (regs) x Vh(T): P*Vh exactly ----
#pragma unroll
        for (int ks = 0; ks < 8; ks++) {
            uint32_t ah[4], al[4];
            ah[0] = cvt_f16x2(sc[2 * ks][1], sc[2 * ks][0]);
            ah[1] = cvt_f16x2(sc[2 * ks][3], sc[2 * ks][2]);
            ah[2] = cvt_f16x2(sc[2 * ks + 1][1], sc[2 * ks + 1][0]);
            ah[3] = cvt_f16x2(sc[2 * ks + 1][3], sc[2 * ks + 1][2]);
            al[0] = cvt_f16x2(sc[2 * ks][1] - f16x2_hi(ah[0]),
                              sc[2 * ks][0] - f16x2_lo(ah[0]));
            al[1] = cvt_f16x2(sc[2 * ks][3] - f16x2_hi(ah[1]),
                              sc[2 * ks][2] - f16x2_lo(ah[1]));
            al[2] = cvt_f16x2(sc[2 * ks + 1][1] - f16x2_hi(ah[2]),
                              sc[2 * ks + 1][0] - f16x2_lo(ah[2]));
            al[3] = cvt_f16x2(sc[2 * ks + 1][3] - f16x2_hi(ah[3]),
                              sc[2 * ks + 1][2] - f16x2_lo(ah[3]));
#pragma unroll
            for (int np = 0; np < 4; np++) {
                uint32_t vh[4];
                ldm_x4(vh, v_base + ks * 32 + np * 16 * VROWB);
                mma16816(o[2 * np],     ah, vh);
                mma16816(o[2 * np + 1], ah, vh + 2);
                mma16816(o[2 * np],     al, vh);
                mma16816(o[2 * np + 1], al, vh + 2);
            }
        }
        __syncthreads();
    }

    // ---- epilogue: normalize, split to fp16 hi/lo, store (B,S,D) ----
#pragma unroll
    for (int rr = 0; rr < 2; rr++) {
        float inv = 1.f / l_s[rr];
        int row = q0 + r0 + er + rr * 8;
        size_t base = ((size_t)b * SEQ + row) * DMODEL + h * HDIM;
#pragma unroll
        for (int nf = 0; nf < 8; nf++) {
            int d = nf * 8 + ec;
            float v0 = o[nf][rr * 2] * inv;
            float v1 = o[nf][rr * 2 + 1] * inv;
            __half2 hh;
            hh.x = __float2half_rn(v0);
            hh.y = __float2half_rn(v1);
            __half2 ll;
            ll.x = __float2half_rn(v0 - __half2float(hh.x));
            ll.y = __float2half_rn(v1 - __half2float(hh.y));
            *(__half2*)(g_ahi + base + d) = hh;
            *(__half2*)(g_alo + base + d) = ll;
        }
    }
}

// ---------------------------------------------------------------------------
// Entry point
// ---------------------------------------------------------------------------
extern "C" void kernel_launch(void* const* d_in, const int* in_sizes, int n_in,
                              void* d_out, int out_size)
{
    const float* x      = (const float*)d_in[0];   // (4, 2048, 1024) fp32
    const int*   mask   = (const int*)d_in[1];     // (4, 2048) int32
    const float* w_qkv  = (const float*)d_in[2];   // (1024, 3072) fp32
    const float* w_out  = (const float*)d_in[3];   // (1024, 1024) fp32
    float*       out    = (float*)d_out;           // (4, 2048, 1024) fp32

    (void)in_sizes; (void)n_in; (void)out_size;

    cudaFuncSetAttribute(mma_gemm_kernel<0>,
                         cudaFuncAttributeMaxDynamicSharedMemorySize, GEMM_SMEM_BYTES);
    cudaFuncSetAttribute(mma_gemm_kernel<1>,
                         cudaFuncAttributeMaxDynamicSharedMemorySize, GEMM_SMEM_BYTES);
    cudaFuncSetAttribute(flash_attn_mma_kernel,
                         cudaFuncAttributeMaxDynamicSharedMemorySize, ATT_SMEM);

    // prep: fp16 splits
    convert_split_kernel<<<(MROWS * DMODEL / 4 + 255) / 256, 256>>>(x, MROWS * DMODEL / 4);
    transpose_split_kernel<<<dim3(NQKV / 32, DMODEL / 32), dim3(32, 8)>>>(w_qkv, 0, NQKV);
    transpose_split_kernel<<<dim3(DMODEL / 32, DMODEL / 32), dim3(32, 8)>>>(w_out, 1, DMODEL);

    // 1) QKV projection -> q/k hi/lo [bh][s][d], v hi transposed [bh][d][s]
    mma_gemm_kernel<0><<<dim3(NQKV / 128, MROWS / 128), 256, GEMM_SMEM_BYTES>>>(nullptr);

    // 2) Tensorized causal flash attention -> g_ahi/g_alo (B,S,D)
    flash_attn_mma_kernel<<<dim3(SEQ / 128, BATCH * NHEADS), 256, ATT_SMEM>>>(mask);

    // 3) Output projection -> d_out
    mma_gemm_kernel<1><<<dim3(DMODEL / 128, MROWS / 128), 256, GEMM_SMEM_BYTES>>>(out);
}